// round 3
// baseline (speedup 1.0000x reference)
#include <cuda_runtime.h>

#define HH 1080
#define WW 1920
#define NPIX (HH * WW)
#define TX 32
#define TY 8
#define HALO 7
#define SW (TX + 2 * HALO)   // 46
#define SH (TY + 2 * HALO)   // 22
#define EPSF 1e-4f
#define LOG2E 1.4426950408889634f

// Scratch: SoA repack of the 11-channel input.
// g_nrmz[i]  = {nx, ny, nz, z}
// g_coldz[i] = {r,  g,  b,  dz}
__device__ float4 g_nrmz[NPIX];
__device__ float4 g_coldz[NPIX];

__global__ void prep_kernel(const float* __restrict__ in) {
    int i = blockIdx.x * blockDim.x + threadIdx.x;
    if (i >= NPIX) return;
    const float* p = in + (size_t)i * 11;
    g_nrmz[i]  = make_float4(p[3], p[4], p[5], p[9]);
    g_coldz[i] = make_float4(p[0], p[1], p[2], p[10]);
}

__device__ __forceinline__ float ex2f(float x) {
    float r;
    asm("ex2.approx.ftz.f32 %0, %1;" : "=f"(r) : "f"(x));
    return r;
}

__global__ void __launch_bounds__(TX * TY) filter_kernel(float* __restrict__ out) {
    __shared__ float4 s_nz[SH][SW];
    __shared__ float4 s_cd[SH][SW];

    const int bx = blockIdx.x * TX;
    const int by = blockIdx.y * TY;
    const int tid = threadIdx.y * TX + threadIdx.x;

    // Cooperative tile load with zero-filled halo.
    // Zero normals -> dot=0 -> clamp to 1e-4 -> ^128 underflows to exactly 0
    // -> w = 0, which reproduces the reference's bounds mask exactly.
    for (int idx = tid; idx < SH * SW; idx += TX * TY) {
        int sy = idx / SW;
        int sx = idx - sy * SW;
        int gy = by + sy - HALO;
        int gx = bx + sx - HALO;
        float4 a = make_float4(0.f, 0.f, 0.f, 0.f);
        float4 b = make_float4(0.f, 0.f, 0.f, 0.f);
        if ((unsigned)gy < (unsigned)HH && (unsigned)gx < (unsigned)WW) {
            int g = gy * WW + gx;
            a = g_nrmz[g];
            b = g_coldz[g];
        }
        s_nz[sy][sx] = a;
        s_cd[sy][sx] = b;
    }
    __syncthreads();

    const int lx = threadIdx.x;
    const int ly = threadIdx.y;

    const float4 cn = s_nz[ly + HALO][lx + HALO];
    const float4 cc = s_cd[ly + HALO][lx + HALO];
    const float nx = cn.x, ny = cn.y, nz = cn.z, z = cn.w;
    const float dz = cc.w;
    // Only used when dz*dist >= EPS, i.e. dz strictly positive there.
    const float rdz = __fdividef(1.0f, dz);

    float ar = 0.f, ag = 0.f, ab = 0.f, aw = 0.f;

#pragma unroll 1
    for (int dy = 0; dy < 15; ++dy) {
        const float4* pn = &s_nz[ly + dy][lx];
        const float4* pc = &s_cd[ly + dy][lx];
        const float dyf = (float)(dy - HALO);
        const float dy2 = dyf * dyf;
#pragma unroll
        for (int dx = 0; dx < 15; ++dx) {
            const float dx2 = (float)((dx - HALO) * (dx - HALO));
            const float4 n4 = pn[dx];
            const float4 c4 = pc[dx];

            // Geometric weight constants (dx2 is a literal after unroll).
            const float d2 = dy2 + dx2;              // dist^2
            const float rdist = rsqrtf(d2);          // +inf at center tap (selected away)
            const float cexp = d2 * (-0.5f * LOG2E); // log2(w_xy)

            // Normal weight: clamp(dot, eps, 1)^128 via 7 squarings.
            float d = n4.x * nx;
            d = fmaf(n4.y, ny, d);
            d = fmaf(n4.z, nz, d);
            d = fminf(fmaxf(d, EPSF), 1.0f);
            float q = d * d;      // ^2
            q = q * q;            // ^4
            q = q * q;            // ^8
            q = q * q;            // ^16
            q = q * q;            // ^32
            q = q * q;            // ^64
            const float wn = q * q; // ^128

            // Depth weight: exp(-|dz_tap|/max(dz*dist, EPS)),
            // branch-free: dz*dist >= EPS  <=>  dz >= EPS*rdist  (dist > 0),
            // continuous at the boundary (both branches equal there).
            const float dzt = n4.w - z;
            const float th = EPSF * rdist;
            const float inv = (dz >= th) ? (rdz * rdist) : 1e4f;
            const float t = fabsf(dzt) * inv;

            // w_xy * w_depth in a single ex2, then * wn.
            const float earg = fmaf(t, -LOG2E, cexp);
            const float w = ex2f(earg) * wn;

            aw += w;
            ar = fmaf(c4.x, w, ar);
            ag = fmaf(c4.y, w, ag);
            ab = fmaf(c4.z, w, ab);
        }
    }

    const float rw = __fdividef(1.0f, fmaxf(aw, EPSF));
    const int o = ((by + ly) * WW + (bx + lx)) * 3;
    out[o + 0] = ar * rw;
    out[o + 1] = ag * rw;
    out[o + 2] = ab * rw;
}

extern "C" void kernel_launch(void* const* d_in, const int* in_sizes, int n_in,
                              void* d_out, int out_size) {
    const float* in = (const float*)d_in[0];
    float* out = (float*)d_out;
    (void)in_sizes; (void)n_in; (void)out_size;

    prep_kernel<<<(NPIX + 255) / 256, 256>>>(in);

    dim3 grid(WW / TX, HH / TY);   // 60 x 135, exact
    dim3 block(TX, TY);
    filter_kernel<<<grid, block>>>(out);
}

// round 5
// speedup vs baseline: 1.2996x; 1.2996x over previous
#include <cuda_runtime.h>

typedef unsigned long long ull;

#define HH 1080
#define WW 1920
#define NPIX (HH * WW)
#define EPSF 1e-4f
#define L2E 1.4426950408889634f

#define BTX 16
#define BTY 4
#define SW 46   // 32 + 14 halo
#define SH 22   // 8 + 14 halo

// SoA repack of the 11-channel input.
__device__ float4 g_nrmz[NPIX];   // {nx, ny, nz, z}
__device__ float4 g_coldz[NPIX];  // {r, g, b, dz}
// Geometry table [dyIdx][parity][jpair] = {cexp_l0, cexp_l1, rdist_l0, rdist_l1}
// dyIdx 0..14 = dy -7..7, dyIdx 15 = masked row. Invalid lanes: cexp=-1e30, rd=0.
__device__ float4 g_tab[16][2][8];

__global__ void prep_kernel(const float* __restrict__ in) {
    int i = blockIdx.x * blockDim.x + threadIdx.x;
    if (i >= NPIX) return;
    const float* p = in + (size_t)i * 11;
    g_nrmz[i]  = make_float4(p[3], p[4], p[5], p[9]);
    g_coldz[i] = make_float4(p[0], p[1], p[2], p[10]);
}

__global__ void tab_kernel() {
    int t = threadIdx.x;              // 256 = 16*2*8
    int dyIdx = t >> 4, par = (t >> 3) & 1, j = t & 7;
    int dy = dyIdx - 7;
    float v[4];
    for (int L = 0; L < 2; ++L) {
        int dx = 2 * j - 7 - par + L;
        bool valid = (dyIdx <= 14) && (dx >= -7) && (dx <= 7);
        float d2 = (float)(dy * dy + dx * dx);
        v[L]     = valid ? (-0.5f * L2E) * d2 : -1e30f;
        v[2 + L] = (valid && d2 > 0.f) ? rsqrtf(d2) : 0.f;
    }
    g_tab[dyIdx][par][j] = make_float4(v[0], v[1], v[2], v[3]);
}

// ---- packed f32x2 helpers ----
__device__ __forceinline__ ull mul2(ull a, ull b) {
    ull d; asm("mul.rn.f32x2 %0, %1, %2;" : "=l"(d) : "l"(a), "l"(b)); return d;
}
__device__ __forceinline__ ull add2(ull a, ull b) {
    ull d; asm("add.rn.f32x2 %0, %1, %2;" : "=l"(d) : "l"(a), "l"(b)); return d;
}
__device__ __forceinline__ ull fma2(ull a, ull b, ull c) {
    ull d; asm("fma.rn.f32x2 %0, %1, %2, %3;" : "=l"(d) : "l"(a), "l"(b), "l"(c)); return d;
}
__device__ __forceinline__ ull abs2(ull a) {
    ull d; asm("and.b64 %0, %1, 0x7FFFFFFF7FFFFFFF;" : "=l"(d) : "l"(a)); return d;
}
__device__ __forceinline__ ull pack2(float lo, float hi) {
    ull r; asm("mov.b64 %0, {%1, %2};" : "=l"(r) : "f"(lo), "f"(hi)); return r;
}
__device__ __forceinline__ void unpk(ull v, float& lo, float& hi) {
    asm("mov.b64 {%0, %1}, %2;" : "=f"(lo), "=f"(hi) : "l"(v));
}
__device__ __forceinline__ float ex2f(float x) {
    float r; asm("ex2.approx.ftz.f32 %0, %1;" : "=f"(r) : "f"(x)); return r;
}
__device__ __forceinline__ float lg2f(float x) {
    float r; asm("lg2.approx.ftz.f32 %0, %1;" : "=f"(r) : "f"(x)); return r;
}

__global__ void __launch_bounds__(BTX * BTY, 8) filter_kernel(float* __restrict__ out) {
    __shared__ float s[8][SH][SW];   // planes: nx ny nz z | r g b dz

    const int bx = blockIdx.x * 32;
    const int by = blockIdx.y * 8;
    const int tx = threadIdx.x, ty = threadIdx.y;
    const int tid = ty * BTX + tx;

    // Cooperative tile load; zero halo => dot=0 => sat=0 => 0^128=0 => w=0,
    // identical to the reference bounds mask (eps^128 underflows to 0 in f32).
    for (int idx = tid; idx < SH * SW; idx += BTX * BTY) {
        int row = idx / SW, col = idx - row * SW;
        int gy = by + row - 7, gx = bx + col - 7;
        float4 a = make_float4(0.f, 0.f, 0.f, 0.f);
        float4 b = make_float4(0.f, 0.f, 0.f, 0.f);
        if ((unsigned)gy < HH && (unsigned)gx < WW) {
            int g = gy * WW + gx;
            a = g_nrmz[g];
            b = g_coldz[g];
        }
        s[0][row][col] = a.x; s[1][row][col] = a.y; s[2][row][col] = a.z; s[3][row][col] = a.w;
        s[4][row][col] = b.x; s[5][row][col] = b.y; s[6][row][col] = b.z; s[7][row][col] = b.w;
    }
    __syncthreads();

    // Per-pixel broadcast state (pixels p = pyi*2+pxi of the 2x2 quad).
    ull nx2[4], ny2[4], nz2[4], mz2[4], rz2[4];
    ull aw2[4], ar2[4], ag2[4], ab2[4];
#pragma unroll
    for (int p = 0; p < 4; ++p) {
        int rr = 2 * ty + (p >> 1) + 7, cc = 2 * tx + (p & 1) + 7;
        float nx = s[0][rr][cc], ny = s[1][rr][cc], nz = s[2][rr][cc];
        float z  = s[3][rr][cc], dz = s[7][rr][cc];
        // inv = 1/max(dz*dist, EPS) == min(rdz*rdist, 1e4) exactly for dz>0;
        // dz<=0 (or sub-1e-9) forces the 1e4 branch for every valid tap.
        float rdz = (dz > 0.f) ? fminf(__fdividef(1.f, dz), 1e9f) : 1e9f;
        nx2[p] = pack2(nx, nx); ny2[p] = pack2(ny, ny); nz2[p] = pack2(nz, nz);
        mz2[p] = pack2(-z, -z); rz2[p] = pack2(rdz, rdz);
        aw2[p] = ar2[p] = ag2[p] = ab2[p] = 0ull;
    }

#pragma unroll 1
    for (int r = 0; r < 16; ++r) {
        const int row = 2 * ty + r;
        const int iA = r;              // dyIdx for pyi=0 (dy=r-7; r=15 masked)
        const int iB = (r + 15) & 15;  // dyIdx for pyi=1 (dy=r-8; r=0 masked)
#pragma unroll
        for (int j = 0; j < 8; ++j) {
            const int c = 2 * tx + 2 * j;   // even word -> aligned LDS.64
            const ull tnx = *(const ull*)&s[0][row][c];
            const ull tny = *(const ull*)&s[1][row][c];
            const ull tnz = *(const ull*)&s[2][row][c];
            const ull tz  = *(const ull*)&s[3][row][c];
            const ull trc = *(const ull*)&s[4][row][c];
            const ull tgc = *(const ull*)&s[5][row][c];
            const ull tbc = *(const ull*)&s[6][row][c];
            const float4 tA0 = g_tab[iA][0][j];
            const float4 tA1 = g_tab[iA][1][j];
            const float4 tB0 = g_tab[iB][0][j];
            const float4 tB1 = g_tab[iB][1][j];
#pragma unroll
            for (int p = 0; p < 4; ++p) {
                const float4 tv = (p == 0) ? tA0 : (p == 1) ? tA1 : (p == 2) ? tB0 : tB1;
                const ull rd2 = pack2(tv.z, tv.w);

                // packed: normal dot, depth delta, reciprocal scale
                ull d2v = fma2(tnz, nz2[p], fma2(tny, ny2[p], mul2(tnx, nx2[p])));
                ull m2  = abs2(add2(tz, mz2[p]));      // |z_tap - z|
                ull iv2 = mul2(rz2[p], rd2);           // rdz * rdist (>=0)

                // per-lane tail: sat, lg2-fold, depth clamp, single ex2
                float d0, d1, m0, m1, i0, i1;
                unpk(d2v, d0, d1); unpk(m2, m0, m1); unpk(iv2, i0, i1);
                float l0 = lg2f(__saturatef(d0));
                float l1 = lg2f(__saturatef(d1));
                i0 = fminf(i0, 1e4f);
                i1 = fminf(i1, 1e4f);
                float e0 = fmaf(l0, 128.f, tv.x);
                float e1 = fmaf(l1, 128.f, tv.y);
                e0 = fmaf(m0 * i0, -L2E, e0);
                e1 = fmaf(m1 * i1, -L2E, e1);
                const ull w2 = pack2(ex2f(e0), ex2f(e1));

                aw2[p] = add2(aw2[p], w2);
                ar2[p] = fma2(trc, w2, ar2[p]);
                ag2[p] = fma2(tgc, w2, ag2[p]);
                ab2[p] = fma2(tbc, w2, ab2[p]);
            }
        }
    }

#pragma unroll
    for (int p = 0; p < 4; ++p) {
        float w0, w1, r0, r1, g0, g1, b0, b1;
        unpk(aw2[p], w0, w1); unpk(ar2[p], r0, r1);
        unpk(ag2[p], g0, g1); unpk(ab2[p], b0, b1);
        const float rw = __fdividef(1.f, fmaxf(w0 + w1, EPSF));
        const int gy = by + 2 * ty + (p >> 1), gx = bx + 2 * tx + (p & 1);
        float* o = out + ((size_t)gy * WW + gx) * 3;
        o[0] = (r0 + r1) * rw;
        o[1] = (g0 + g1) * rw;
        o[2] = (b0 + b1) * rw;
    }
}

extern "C" void kernel_launch(void* const* d_in, const int* in_sizes, int n_in,
                              void* d_out, int out_size) {
    const float* in = (const float*)d_in[0];
    float* out = (float*)d_out;
    (void)in_sizes; (void)n_in; (void)out_size;

    prep_kernel<<<(NPIX + 255) / 256, 256>>>(in);
    tab_kernel<<<1, 256>>>();

    dim3 grid(WW / 32, HH / 8);   // 60 x 135, exact
    dim3 block(BTX, BTY);
    filter_kernel<<<grid, block>>>(out);
}

// round 8
// speedup vs baseline: 1.4522x; 1.1174x over previous
#include <cuda_runtime.h>

typedef unsigned long long ull;

#define HH 1080
#define WW 1920
#define NPIX (HH * WW)
#define EPSF 1e-4f
#define L2E 1.4426950408889634f
#define CLAMPV (-14426.950408889634f)   /* -L2E * 1e4 */

#define BTX 16
#define BTY 4
#define SW 46   // 32 + 14 halo
#define SH 22   // 8 + 14 halo

// SoA repack of the 11-channel input.
__device__ float4 g_nrmz[NPIX];   // {nx, ny, nz, z}
__device__ float4 g_coldz[NPIX];  // {r, g, b, dz}
// Geometry table [dyIdx][parity][jpair] = {cexp_l0, cexp_l1, rdist_l0, rdist_l1}
// dyIdx 0..14 = dy -7..7, dyIdx 15 = masked row. Invalid lanes: cexp=-1e30, rd=0.
__device__ float4 g_tab[16][2][8];

__global__ void prep_kernel(const float* __restrict__ in) {
    int i = blockIdx.x * blockDim.x + threadIdx.x;
    if (i >= NPIX) return;
    const float* p = in + (size_t)i * 11;
    g_nrmz[i]  = make_float4(p[3], p[4], p[5], p[9]);
    g_coldz[i] = make_float4(p[0], p[1], p[2], p[10]);
}

__global__ void tab_kernel() {
    int t = threadIdx.x;              // 256 = 16*2*8
    int dyIdx = t >> 4, par = (t >> 3) & 1, j = t & 7;
    int dy = dyIdx - 7;
    float v[4];
    for (int L = 0; L < 2; ++L) {
        int dx = 2 * j - 7 - par + L;
        bool valid = (dyIdx <= 14) && (dx >= -7) && (dx <= 7);
        float d2 = (float)(dy * dy + dx * dx);
        v[L]     = valid ? (-0.5f * L2E) * d2 : -1e30f;
        v[2 + L] = (valid && d2 > 0.f) ? rsqrtf(d2) : 0.f;
    }
    g_tab[dyIdx][par][j] = make_float4(v[0], v[1], v[2], v[3]);
}

// ---- packed f32x2 helpers ----
__device__ __forceinline__ ull mul2(ull a, ull b) {
    ull d; asm("mul.rn.f32x2 %0, %1, %2;" : "=l"(d) : "l"(a), "l"(b)); return d;
}
__device__ __forceinline__ ull add2(ull a, ull b) {
    ull d; asm("add.rn.f32x2 %0, %1, %2;" : "=l"(d) : "l"(a), "l"(b)); return d;
}
__device__ __forceinline__ ull fma2(ull a, ull b, ull c) {
    ull d; asm("fma.rn.f32x2 %0, %1, %2, %3;" : "=l"(d) : "l"(a), "l"(b), "l"(c)); return d;
}
__device__ __forceinline__ ull abs2(ull a) {
    ull d; asm("and.b64 %0, %1, 0x7FFFFFFF7FFFFFFF;" : "=l"(d) : "l"(a)); return d;
}
__device__ __forceinline__ ull pack2(float lo, float hi) {
    ull r; asm("mov.b64 %0, {%1, %2};" : "=l"(r) : "f"(lo), "f"(hi)); return r;
}
__device__ __forceinline__ void unpk(ull v, float& lo, float& hi) {
    asm("mov.b64 {%0, %1}, %2;" : "=f"(lo), "=f"(hi) : "l"(v));
}
__device__ __forceinline__ float ex2f(float x) {
    float r; asm("ex2.approx.ftz.f32 %0, %1;" : "=f"(r) : "f"(x)); return r;
}
__device__ __forceinline__ float lg2f(float x) {
    float r; asm("lg2.approx.ftz.f32 %0, %1;" : "=f"(r) : "f"(x)); return r;
}

__global__ void __launch_bounds__(BTX * BTY, 7) filter_kernel(float* __restrict__ out) {
    __shared__ float s[7][SH][SW];      // planes: nx ny nz z | r g b
    __shared__ ull  stab[16][2][8][2];  // [dyIdx][par][j][0]=ce2 pair, [1]=rd2 pair

    const int bx = blockIdx.x * 32;
    const int by = blockIdx.y * 8;
    const int tx = threadIdx.x, ty = threadIdx.y;
    const int tid = ty * BTX + tx;

    // Copy geometry table into smem (4KB, packed as ull pairs already).
    {
        const ull* src = (const ull*)g_tab;
        ull* dst = (ull*)stab;
        for (int i = tid; i < 16 * 2 * 8 * 2; i += BTX * BTY) dst[i] = src[i];
    }

    // Cooperative tile load; zero halo => dot=0 => sat=0 => lg2=-inf => w=0,
    // identical to the reference bounds mask (eps^128 underflows to 0 in f32).
    for (int idx = tid; idx < SH * SW; idx += BTX * BTY) {
        int row = idx / SW, col = idx - row * SW;
        int gy = by + row - 7, gx = bx + col - 7;
        float4 a = make_float4(0.f, 0.f, 0.f, 0.f);
        float4 b = make_float4(0.f, 0.f, 0.f, 0.f);
        if ((unsigned)gy < HH && (unsigned)gx < WW) {
            int g = gy * WW + gx;
            a = g_nrmz[g];
            b = g_coldz[g];
        }
        s[0][row][col] = a.x; s[1][row][col] = a.y; s[2][row][col] = a.z;
        s[3][row][col] = a.w;
        s[4][row][col] = b.x; s[5][row][col] = b.y; s[6][row][col] = b.z;
    }
    __syncthreads();

    const ull C128 = pack2(128.f, 128.f);

    // Per-pixel broadcast state (pixels p = pyi*2+pxi of the 2x2 quad).
    ull nx2[4], ny2[4], nz2[4], mz2[4], rzs2[4];
    ull aw2[4], ar2[4], ag2[4], ab2[4];
#pragma unroll
    for (int p = 0; p < 4; ++p) {
        const int pyi = p >> 1, pxi = p & 1;
        const int rr = 2 * ty + pyi + 7, cc = 2 * tx + pxi + 7;
        const float nx = s[0][rr][cc], ny = s[1][rr][cc], nz = s[2][rr][cc];
        const float z  = s[3][rr][cc];
        const int gy = by + 2 * ty + pyi, gx = bx + 2 * tx + pxi;
        const float dz = g_coldz[(size_t)gy * WW + gx].w;
        // inv = 1/max(dz*dist, EPS) == min(rdz*rdist, 1e4) exactly for dz>0;
        // dz<=0 (or sub-1e-9) forces the 1e4 branch for every valid tap.
        const float rdz = (dz > 0.f) ? fminf(__fdividef(1.f, dz), 1e9f) : 1e9f;
        const float rzs = -L2E * rdz;   // fold -log2(e) into the reciprocal
        nx2[p] = pack2(nx, nx); ny2[p] = pack2(ny, ny); nz2[p] = pack2(nz, nz);
        mz2[p] = pack2(-z, -z); rzs2[p] = pack2(rzs, rzs);
        aw2[p] = ar2[p] = ag2[p] = ab2[p] = 0ull;
    }

#pragma unroll 1
    for (int r = 0; r < 16; ++r) {
        const int row = 2 * ty + r;
        const int iA = r;              // dyIdx for pyi=0 (dy=r-7; r=15 masked)
        const int iB = (r + 15) & 15;  // dyIdx for pyi=1 (dy=r-8; r=0 masked)
#pragma unroll
        for (int j = 0; j < 8; ++j) {
            const int c = 2 * tx + 2 * j;   // even word -> aligned LDS.64
            const ull tnx = *(const ull*)&s[0][row][c];
            const ull tny = *(const ull*)&s[1][row][c];
            const ull tnz = *(const ull*)&s[2][row][c];
            const ull tz  = *(const ull*)&s[3][row][c];
            const ull trc = *(const ull*)&s[4][row][c];
            const ull tgc = *(const ull*)&s[5][row][c];
            const ull tbc = *(const ull*)&s[6][row][c];
            // pre-packed ce/rd pairs, uniform broadcast LDS.64
            const ull ceT[4] = { stab[iA][0][j][0], stab[iA][1][j][0],
                                 stab[iB][0][j][0], stab[iB][1][j][0] };
            const ull rdT[4] = { stab[iA][0][j][1], stab[iA][1][j][1],
                                 stab[iB][0][j][1], stab[iB][1][j][1] };
#pragma unroll
            for (int p = 0; p < 4; ++p) {
                // packed normal dot
                ull d2v = fma2(tnz, nz2[p], fma2(tny, ny2[p], mul2(tnx, nx2[p])));
                float d0, d1; unpk(d2v, d0, d1);
                // wn in log2 domain: 128*lg2(sat(d)) + cexp
                const ull l2 = pack2(lg2f(__saturatef(d0)), lg2f(__saturatef(d1)));
                const ull el = fma2(l2, C128, ceT[p]);
                // depth term: e += |z_t - z| * clamp(-L2E*rdz*rdist, >= -L2E*1e4)
                const ull m2 = abs2(add2(tz, mz2[p]));
                ull iv = mul2(rzs2[p], rdT[p]);
                float i0, i1; unpk(iv, i0, i1);
                iv = pack2(fmaxf(i0, CLAMPV), fmaxf(i1, CLAMPV));
                const ull e2 = fma2(m2, iv, el);
                float e0, e1; unpk(e2, e0, e1);
                const ull w2 = pack2(ex2f(e0), ex2f(e1));

                aw2[p] = add2(aw2[p], w2);
                ar2[p] = fma2(trc, w2, ar2[p]);
                ag2[p] = fma2(tgc, w2, ag2[p]);
                ab2[p] = fma2(tbc, w2, ab2[p]);
            }
        }
    }

#pragma unroll
    for (int p = 0; p < 4; ++p) {
        float w0, w1, r0, r1, g0, g1, b0, b1;
        unpk(aw2[p], w0, w1); unpk(ar2[p], r0, r1);
        unpk(ag2[p], g0, g1); unpk(ab2[p], b0, b1);
        const float rw = __fdividef(1.f, fmaxf(w0 + w1, EPSF));
        const int gy = by + 2 * ty + (p >> 1), gx = bx + 2 * tx + (p & 1);
        float* o = out + ((size_t)gy * WW + gx) * 3;
        o[0] = (r0 + r1) * rw;
        o[1] = (g0 + g1) * rw;
        o[2] = (b0 + b1) * rw;
    }
}

extern "C" void kernel_launch(void* const* d_in, const int* in_sizes, int n_in,
                              void* d_out, int out_size) {
    const float* in = (const float*)d_in[0];
    float* out = (float*)d_out;
    (void)in_sizes; (void)n_in; (void)out_size;

    prep_kernel<<<(NPIX + 255) / 256, 256>>>(in);
    tab_kernel<<<1, 256>>>();

    dim3 grid(WW / 32, HH / 8);   // 60 x 135, exact
    dim3 block(BTX, BTY);
    filter_kernel<<<grid, block>>>(out);
}

// round 10
// speedup vs baseline: 1.9200x; 1.3221x over previous
#include <cuda_runtime.h>

typedef unsigned long long ull;

#define HH 1080
#define WW 1920
#define NPIX (HH * WW)
#define EPSF 1e-4f
#define L2E 1.4426950408889634f
#define CLAMPV (-14426.950408889634f)   /* -L2E * 1e4 */

#define BTX 16
#define BTY 4
#define SW 46   // 32 + 14 halo
#define SH 22   // 8 + 14 halo

// SoA repack of the 11-channel input.
__device__ float4 g_nrmz[NPIX];   // {nx, ny, nz, z}
__device__ float4 g_coldz[NPIX];  // {r, g, b, dz}

// ---- compile-time geometry table (constant memory, LDCU path) ----
// ce[dyIdx][par][j] = packed pair {cexp_l0, cexp_l1}, rd = {rdist_l0, rdist_l1}
// dyIdx 0..14 <=> dy -7..7. Lane L of pair (par,j) is dx = 2j-7-par+L.
// Valid iff dy^2+dx^2 <= 40 (disc truncation: dropped taps have w <= 1.24e-9).
// Invalid lanes: cexp=-1e30 -> ex2 -> 0, rd=0.
struct alignas(8) F2 { float x, y; };
struct Tab { F2 ce[15][2][8]; F2 rd[15][2][8]; };

constexpr double csqrt(double x) {
    double g = x > 1.0 ? x : 1.0;
    for (int i = 0; i < 60; ++i) g = 0.5 * (g + x / g);
    return g;
}
constexpr Tab make_tab() {
    Tab t{};
    for (int i = 0; i < 15; ++i)
        for (int par = 0; par < 2; ++par)
            for (int j = 0; j < 8; ++j) {
                int dy = i - 7;
                float v[2] = {}, r[2] = {};
                for (int L = 0; L < 2; ++L) {
                    int dx = 2 * j - 7 - par + L;
                    int d2i = dy * dy + dx * dx;
                    bool valid = (d2i <= 40);
                    v[L] = valid ? (float)(-0.5 * 1.4426950408889634 * (double)d2i)
                                 : -1e30f;
                    r[L] = (valid && d2i > 0) ? (float)(1.0 / csqrt((double)d2i)) : 0.f;
                }
                t.ce[i][par][j] = F2{v[0], v[1]};
                t.rd[i][par][j] = F2{r[0], r[1]};
            }
    return t;
}
__constant__ Tab c_tab = make_tab();

__global__ void prep_kernel(const float* __restrict__ in) {
    int i = blockIdx.x * blockDim.x + threadIdx.x;
    if (i >= NPIX) return;
    const float* p = in + (size_t)i * 11;
    g_nrmz[i]  = make_float4(p[3], p[4], p[5], p[9]);
    g_coldz[i] = make_float4(p[0], p[1], p[2], p[10]);
}

// ---- packed f32x2 helpers ----
__device__ __forceinline__ ull mul2(ull a, ull b) {
    ull d; asm("mul.rn.f32x2 %0, %1, %2;" : "=l"(d) : "l"(a), "l"(b)); return d;
}
__device__ __forceinline__ ull add2(ull a, ull b) {
    ull d; asm("add.rn.f32x2 %0, %1, %2;" : "=l"(d) : "l"(a), "l"(b)); return d;
}
__device__ __forceinline__ ull fma2(ull a, ull b, ull c) {
    ull d; asm("fma.rn.f32x2 %0, %1, %2, %3;" : "=l"(d) : "l"(a), "l"(b), "l"(c)); return d;
}
__device__ __forceinline__ ull abs2(ull a) {
    ull d; asm("and.b64 %0, %1, 0x7FFFFFFF7FFFFFFF;" : "=l"(d) : "l"(a)); return d;
}
__device__ __forceinline__ ull pack2(float lo, float hi) {
    ull r; asm("mov.b64 %0, {%1, %2};" : "=l"(r) : "f"(lo), "f"(hi)); return r;
}
__device__ __forceinline__ void unpk(ull v, float& lo, float& hi) {
    asm("mov.b64 {%0, %1}, %2;" : "=f"(lo), "=f"(hi) : "l"(v));
}
__device__ __forceinline__ float ex2f(float x) {
    float r; asm("ex2.approx.ftz.f32 %0, %1;" : "=f"(r) : "f"(x)); return r;
}
__device__ __forceinline__ float lg2f(float x) {
    float r; asm("lg2.approx.ftz.f32 %0, %1;" : "=f"(r) : "f"(x)); return r;
}

// One (tap-pair, pixel-context) update. Validated math from R8:
//   w = ex2(128*lg2(sat(dot)) + cexp + |z_t-z|*max(-L2E*rdz*rdist, -L2E*1e4))
__device__ __forceinline__ void tap_ctx(
    ull tnx, ull tny, ull tnz, ull tz, ull trc, ull tgc, ull tbc,
    ull ce, ull rd, ull C128,
    ull nxp, ull nyp, ull nzp, ull mzp, ull rzsp,
    ull& aw, ull& ar, ull& ag, ull& ab)
{
    ull d2v = fma2(tnz, nzp, fma2(tny, nyp, mul2(tnx, nxp)));
    float d0, d1; unpk(d2v, d0, d1);
    const ull l2 = pack2(lg2f(__saturatef(d0)), lg2f(__saturatef(d1)));
    const ull el = fma2(l2, C128, ce);
    const ull m2 = abs2(add2(tz, mzp));
    ull iv = mul2(rzsp, rd);
    float i0, i1; unpk(iv, i0, i1);
    iv = pack2(fmaxf(i0, CLAMPV), fmaxf(i1, CLAMPV));
    const ull e2 = fma2(m2, iv, el);
    float e0, e1; unpk(e2, e0, e1);
    const ull w2 = pack2(ex2f(e0), ex2f(e1));
    aw = add2(aw, w2);
    ar = fma2(trc, w2, ar);
    ag = fma2(tgc, w2, ag);
    ab = fma2(tbc, w2, ab);
}

// Row macro: context A = pixel-row 0 (dy = r-7, table row r),
//            context B = pixel-row 1 (dy = r-8, table row r-1).
#define ROW(RV, JLO, JCNT, DA, DB) do {                                        \
    const int r_ = (RV);                                                       \
    const int row_ = 2 * ty + r_;                                              \
    const float* sp0 = &s[0][row_][2 * tx];                                    \
    const float* sp1 = &s[1][row_][2 * tx];                                    \
    const float* sp2 = &s[2][row_][2 * tx];                                    \
    const float* sp3 = &s[3][row_][2 * tx];                                    \
    const float* sp4 = &s[4][row_][2 * tx];                                    \
    const float* sp5 = &s[5][row_][2 * tx];                                    \
    const float* sp6 = &s[6][row_][2 * tx];                                    \
    const F2* ceA = &c_tab.ce[r_][0][0];                                       \
    const F2* rdA = &c_tab.rd[r_][0][0];                                       \
    const F2* ceB = &c_tab.ce[r_ - 1][0][0];                                   \
    const F2* rdB = &c_tab.rd[r_ - 1][0][0];                                   \
    _Pragma("unroll")                                                          \
    for (int jj = 0; jj < (JCNT); ++jj) {                                      \
        const int j = (JLO) + jj, cc_ = 2 * j;                                 \
        const ull tnx = *(const ull*)(sp0 + cc_);                              \
        const ull tny = *(const ull*)(sp1 + cc_);                              \
        const ull tnz = *(const ull*)(sp2 + cc_);                              \
        const ull tz  = *(const ull*)(sp3 + cc_);                              \
        const ull trc = *(const ull*)(sp4 + cc_);                              \
        const ull tgc = *(const ull*)(sp5 + cc_);                              \
        const ull tbc = *(const ull*)(sp6 + cc_);                              \
        if (DA) {                                                              \
            tap_ctx(tnx, tny, tnz, tz, trc, tgc, tbc,                          \
                    *(const ull*)(ceA + j), *(const ull*)(rdA + j), C128,      \
                    nx2[0], ny2[0], nz2[0], mz2[0], rzs2[0],                   \
                    aw2[0], ar2[0], ag2[0], ab2[0]);                           \
            tap_ctx(tnx, tny, tnz, tz, trc, tgc, tbc,                          \
                    *(const ull*)(ceA + 8 + j), *(const ull*)(rdA + 8 + j),    \
                    C128,                                                      \
                    nx2[1], ny2[1], nz2[1], mz2[1], rzs2[1],                   \
                    aw2[1], ar2[1], ag2[1], ab2[1]);                           \
        }                                                                      \
        if (DB) {                                                              \
            tap_ctx(tnx, tny, tnz, tz, trc, tgc, tbc,                          \
                    *(const ull*)(ceB + j), *(const ull*)(rdB + j), C128,      \
                    nx2[2], ny2[2], nz2[2], mz2[2], rzs2[2],                   \
                    aw2[2], ar2[2], ag2[2], ab2[2]);                           \
            tap_ctx(tnx, tny, tnz, tz, trc, tgc, tbc,                          \
                    *(const ull*)(ceB + 8 + j), *(const ull*)(rdB + 8 + j),    \
                    C128,                                                      \
                    nx2[3], ny2[3], nz2[3], mz2[3], rzs2[3],                   \
                    aw2[3], ar2[3], ag2[3], ab2[3]);                           \
        }                                                                      \
    }                                                                          \
} while (0)

__global__ void __launch_bounds__(BTX * BTY, 8) filter_kernel(float* __restrict__ out) {
    __shared__ float s[7][SH][SW];      // planes: nx ny nz z | r g b

    const int bx = blockIdx.x * 32;
    const int by = blockIdx.y * 8;
    const int tx = threadIdx.x, ty = threadIdx.y;
    const int tid = ty * BTX + tx;

    // Cooperative tile load; zero halo => dot=0 => sat=0 => lg2=-inf => w=0,
    // identical to the reference bounds mask (eps^128 underflows to 0 in f32).
    for (int idx = tid; idx < SH * SW; idx += BTX * BTY) {
        int row = idx / SW, col = idx - row * SW;
        int gy = by + row - 7, gx = bx + col - 7;
        float4 a = make_float4(0.f, 0.f, 0.f, 0.f);
        float4 b = make_float4(0.f, 0.f, 0.f, 0.f);
        if ((unsigned)gy < HH && (unsigned)gx < WW) {
            int g = gy * WW + gx;
            a = g_nrmz[g];
            b = g_coldz[g];
        }
        s[0][row][col] = a.x; s[1][row][col] = a.y; s[2][row][col] = a.z;
        s[3][row][col] = a.w;
        s[4][row][col] = b.x; s[5][row][col] = b.y; s[6][row][col] = b.z;
    }
    __syncthreads();

    const ull C128 = 0x4300000043000000ULL;   // {128.0f, 128.0f}

    // Per-pixel broadcast state (pixels p = pyi*2+pxi of the 2x2 quad).
    ull nx2[4], ny2[4], nz2[4], mz2[4], rzs2[4];
    ull aw2[4], ar2[4], ag2[4], ab2[4];
#pragma unroll
    for (int p = 0; p < 4; ++p) {
        const int pyi = p >> 1, pxi = p & 1;
        const int rr = 2 * ty + pyi + 7, cc = 2 * tx + pxi + 7;
        const float nx = s[0][rr][cc], ny = s[1][rr][cc], nz = s[2][rr][cc];
        const float z  = s[3][rr][cc];
        const int gy = by + 2 * ty + pyi, gx = bx + 2 * tx + pxi;
        const float dz = g_coldz[(size_t)gy * WW + gx].w;
        // inv = 1/max(dz*dist, EPS) == min(rdz*rdist, 1e4) exactly for dz>0;
        // dz<=0 forces the 1e4 branch for every valid tap.
        const float rdz = (dz > 0.f) ? fminf(__fdividef(1.f, dz), 1e9f) : 1e9f;
        const float rzs = -L2E * rdz;   // fold -log2(e) into the reciprocal
        nx2[p] = pack2(nx, nx); ny2[p] = pack2(ny, ny); nz2[p] = pack2(nz, nz);
        mz2[p] = pack2(-z, -z); rzs2[p] = pack2(rzs, rzs);
        aw2[p] = ar2[p] = ag2[p] = ab2[p] = 0ull;
    }

    // Disc-truncated tap sweep (d^2 <= 40), rows grouped by j-pair count.
    // Pair-width per row: hwm=max(hw(|r-7|), hw(|r-8|)), hw: 0..2->6,3->5,4->4,5->3,6->2.
#pragma unroll 1
    for (int r = 5; r <= 10; ++r) ROW(r, 0, 8, 1, 1);   // full-width rows
    {
        const int rB[4] = {3, 4, 11, 12};
#pragma unroll 1
        for (int k = 0; k < 4; ++k) ROW(rB[k], 1, 6, 1, 1);
    }
    {
        const int rA[2] = {2, 13};
#pragma unroll 1
        for (int k = 0; k < 2; ++k) ROW(rA[k], 2, 4, 1, 1);
    }
    ROW(1, 2, 4, 1, 0);    // dy=-6 valid only for pixel-row 0
    ROW(14, 2, 4, 0, 1);   // dy=+6 valid only for pixel-row 1

#pragma unroll
    for (int p = 0; p < 4; ++p) {
        float w0, w1, r0, r1, g0, g1, b0, b1;
        unpk(aw2[p], w0, w1); unpk(ar2[p], r0, r1);
        unpk(ag2[p], g0, g1); unpk(ab2[p], b0, b1);
        const float rw = __fdividef(1.f, fmaxf(w0 + w1, EPSF));
        const int gy = by + 2 * ty + (p >> 1), gx = bx + 2 * tx + (p & 1);
        float* o = out + ((size_t)gy * WW + gx) * 3;
        o[0] = (r0 + r1) * rw;
        o[1] = (g0 + g1) * rw;
        o[2] = (b0 + b1) * rw;
    }
}

extern "C" void kernel_launch(void* const* d_in, const int* in_sizes, int n_in,
                              void* d_out, int out_size) {
    const float* in = (const float*)d_in[0];
    float* out = (float*)d_out;
    (void)in_sizes; (void)n_in; (void)out_size;

    prep_kernel<<<(NPIX + 255) / 256, 256>>>(in);

    dim3 grid(WW / 32, HH / 8);   // 60 x 135, exact
    dim3 block(BTX, BTY);
    filter_kernel<<<grid, block>>>(out);
}